// round 7
// baseline (speedup 1.0000x reference)
#include <cuda_runtime.h>
#include <cstdint>

// TDLoss: GAE backward scan + squared TD loss. [T,B] time-major, T=256, B=65536.
// R7: TMA bulk-copy (cp.async.bulk + mbarrier) staging pipeline, depth 16.
// In-flight bytes are decoupled from registers AND from per-thread LSU issue:
// one thread per block issues 512B bulk copies; 512 blk x 16 stages x 2.5KB
// = 20MB outstanding chip-wide.

namespace {
constexpr int   T_STEPS = 256;
constexpr int   B_COLS  = 65536;
constexpr int   W2      = B_COLS / 2;     // float2 columns = 32768
constexpr int   NTHR    = 64;             // threads per block = tile columns
constexpr int   NBLK    = W2 / NTHR;      // 512 blocks
constexpr int   D       = 16;             // pipeline depth
constexpr int   TILE_B  = NTHR * 8;       // 512 bytes per array-row per block
constexpr float GAMMA   = 0.99f;
constexpr float LAMBDA  = 0.95f;
constexpr int   STEP_TYPE_LAST = 2;
}

__device__ __forceinline__ uint32_t smem_u32(const void* p) {
    return (uint32_t)__cvta_generic_to_shared(p);
}
__device__ __forceinline__ void mbar_init(uint32_t mbar, uint32_t count) {
    asm volatile("mbarrier.init.shared.b64 [%0], %1;" :: "r"(mbar), "r"(count) : "memory");
}
__device__ __forceinline__ void mbar_expect_tx(uint32_t mbar, uint32_t bytes) {
    asm volatile("mbarrier.arrive.expect_tx.shared.b64 _, [%0], %1;"
                 :: "r"(mbar), "r"(bytes) : "memory");
}
__device__ __forceinline__ void mbar_wait(uint32_t mbar, uint32_t parity) {
    uint32_t done;
    asm volatile(
        "{\n\t.reg .pred p;\n\t"
        "mbarrier.try_wait.parity.acquire.cta.shared::cta.b64 p, [%1], %2;\n\t"
        "selp.b32 %0, 1, 0, p;\n\t}"
        : "=r"(done) : "r"(mbar), "r"(parity) : "memory");
    if (!done) {
        asm volatile(
            "{\n\t.reg .pred P1;\n\t"
            "WL_%=:\n\t"
            "mbarrier.try_wait.parity.acquire.cta.shared::cta.b64 P1, [%0], %1, 0x989680;\n\t"
            "@P1 bra.uni WD_%=;\n\t"
            "bra.uni WL_%=;\n\t"
            "WD_%=:\n\t}"
            :: "r"(mbar), "r"(parity) : "memory");
    }
}
__device__ __forceinline__ void bulk_g2s(uint32_t smem_dst, const void* gmem_src,
                                         uint32_t bytes, uint32_t mbar) {
    asm volatile(
        "cp.async.bulk.shared::cta.global.mbarrier::complete_tx::bytes [%0], [%1], %2, [%3];"
        :: "r"(smem_dst), "l"(gmem_src), "r"(bytes), "r"(mbar) : "memory");
}

__global__ void __launch_bounds__(NTHR)
td_loss_kernel(const float2* __restrict__ reward,
               const int2*   __restrict__ step_type,
               const float2* __restrict__ discount,
               const float2* __restrict__ value,
               const float2* __restrict__ tv,
               float2*       __restrict__ out)
{
    __shared__ alignas(128) float2 s_r [D][NTHR];
    __shared__ alignas(128) float2 s_d [D][NTHR];
    __shared__ alignas(128) float2 s_tv[D][NTHR];
    __shared__ alignas(128) int2   s_st[D][NTHR];
    __shared__ alignas(128) float2 s_v [D][NTHR];
    __shared__ alignas(8)  uint64_t mbar[D];

    const int tid  = threadIdx.x;
    const int col0 = blockIdx.x * NTHR;       // first float2 column of tile
    const int c    = col0 + tid;              // this thread's column

    if (tid == 0) {
        #pragma unroll
        for (int s = 0; s < D; ++s)
            mbar_init(smem_u32(&mbar[s]), 1); // 1 arrival: the expect_tx
    }
    __syncthreads();

    // Stage issue: fetch the 5 rows needed for scan step k (t = 254-k) into slot s.
    auto issue = [&](int k, int s) {
        const int t  = T_STEPS - 2 - k;
        const int i1 = (t + 1) * W2 + col0;
        const int i0 = t * W2 + col0;
        const uint32_t mb = smem_u32(&mbar[s]);
        mbar_expect_tx(mb, 5 * TILE_B);
        bulk_g2s(smem_u32(&s_r [s][0]), reward    + i1, TILE_B, mb);
        bulk_g2s(smem_u32(&s_d [s][0]), discount  + i1, TILE_B, mb);
        bulk_g2s(smem_u32(&s_tv[s][0]), tv        + i0, TILE_B, mb);
        bulk_g2s(smem_u32(&s_st[s][0]), step_type + i0, TILE_B, mb);
        bulk_g2s(smem_u32(&s_v [s][0]), value     + i0, TILE_B, mb);
    };

    // Zero the last time row (output is poisoned by the harness).
    out[(T_STEPS - 1) * W2 + c] = make_float2(0.f, 0.f);

    // Prologue: fill the pipeline.
    if (tid == 0) {
        for (int k = 0; k < D; ++k)
            issue(k, k);
    }

    float2 adv = make_float2(0.f, 0.f);
    float2 tvn = tv[(T_STEPS - 1) * W2 + c];   // target_value[t+1] carry

    for (int k = 0; k < T_STEPS - 1; ++k) {
        const int s      = k % D;
        const uint32_t p = (uint32_t)((k / D) & 1);

        mbar_wait(smem_u32(&mbar[s]), p);

        const float2 r   = s_r [s][tid];
        const float2 d   = s_d [s][tid];
        const float2 tvc = s_tv[s][tid];
        const int2   st  = s_st[s][tid];
        const float2 v   = s_v [s][tid];

        float2 o;
        #define LANE(X)                                                     \
        {                                                                   \
            const float disc  = d.X * GAMMA;                                \
            const float delta = fmaf(disc, tvn.X, r.X) - tvc.X;             \
            const float wd    = disc * LAMBDA;                              \
            float a           = fmaf(wd, adv.X, delta);                     \
            a                 = (st.X == STEP_TYPE_LAST) ? 0.f : a;         \
            adv.X             = a;                                          \
            const float diff  = v.X - (a + tvc.X);                          \
            o.X               = diff * diff;                                \
        }
        LANE(x) LANE(y)
        #undef LANE

        out[(T_STEPS - 2 - k) * W2 + c] = o;
        tvn = tvc;

        // All threads have consumed slot s -> safe to refill.
        __syncthreads();
        if (tid == 0 && (k + D) < T_STEPS - 1)
            issue(k + D, s);
    }
}

extern "C" void kernel_launch(void* const* d_in, const int* in_sizes, int n_in,
                              void* d_out, int out_size)
{
    const float2* reward    = (const float2*)d_in[0];
    const int2*   step_type = (const int2*)  d_in[1];
    const float2* discount  = (const float2*)d_in[2];
    const float2* value     = (const float2*)d_in[3];
    const float2* tv        = (const float2*)d_in[4];
    float2*       out       = (float2*)d_out;

    td_loss_kernel<<<NBLK, NTHR>>>(reward, step_type, discount, value, tv, out);
}